// round 5
// baseline (speedup 1.0000x reference)
#include <cuda_runtime.h>
#include <cuda_bf16.h>

#define RM_EPS 1e-10f
#define MIN_DEPTH 0.1f
#define MAX_DEPTH 100.0f

constexpr int S_SAMP = 128;        // samples per ray
constexpr int S_INT  = S_SAMP - 1; // 127 intervals
constexpr int WARPS_PER_BLOCK = 8;

// Per-warp shared layout (640 floats = 2560 B):
//   [0,384)   colors for this ray (128 samples * 3)
//   [384,512) density_logits
//   [512,640) depths
// After compute, [0,384) is reused to stage weights/alpha/depths_mid for
// coalesced writeback.
__global__ __launch_bounds__(WARPS_PER_BLOCK * 32)
void mip_ray_marcher_kernel(const float* __restrict__ colors,
                            const float* __restrict__ dlog,
                            const float* __restrict__ depths,
                            float* __restrict__ out,
                            int n_rays)
{
    __shared__ __align__(16) float smem[WARPS_PER_BLOCK][640];

    const int warp = threadIdx.x >> 5;
    const int lane = threadIdx.x & 31;
    const int ray  = blockIdx.x * WARPS_PER_BLOCK + warp;
    if (ray >= n_rays) return;

    float* scol = smem[warp];          // 384 floats
    float* sdl  = smem[warp] + 384;    // 128 floats
    float* sdep = smem[warp] + 512;    // 128 floats

    // ---- cooperative, coalesced float4 loads of this ray's data ----
    {
        const float4* c4 = (const float4*)(colors + (size_t)ray * (S_SAMP * 3));
        float4* s4 = (float4*)scol;
        s4[lane]      = c4[lane];
        s4[lane + 32] = c4[lane + 32];
        s4[lane + 64] = c4[lane + 64];

        const float4* d4 = (const float4*)(dlog + (size_t)ray * S_SAMP);
        ((float4*)sdl)[lane] = d4[lane];

        const float4* z4 = (const float4*)(depths + (size_t)ray * S_SAMP);
        ((float4*)sdep)[lane] = z4[lane];
    }
    __syncwarp();

    // ---- per-lane: 4 intervals (lane 31: 3 valid) ----
    float alpha[4], om[4], dmid[4];
    float r0 = 0.f, r1 = 0.f, r2 = 0.f, wsum = 0.f, wdsum = 0.f;

    #pragma unroll
    for (int k = 0; k < 4; k++) {
        int i = lane * 4 + k;
        if (i < S_INT) {
            float dlm  = 0.5f * (sdl[i] + sdl[i + 1]) - 1.0f;
            // numerically stable softplus: max(x,0) + log1p(exp(-|x|))
            float dens = fmaxf(dlm, 0.0f) + log1pf(expf(-fabsf(dlm)));
            float delta = sdep[i + 1] - sdep[i];
            float a = 1.0f - expf(-dens * delta);
            alpha[k] = a;
            om[k]    = 1.0f - a + RM_EPS;
            dmid[k]  = 0.5f * (sdep[i] + sdep[i + 1]);
        } else {
            alpha[k] = 0.0f;
            om[k]    = 1.0f;   // identity for the scan
            dmid[k]  = 0.0f;
        }
    }

    // ---- warp-level cumprod: local product -> inclusive shfl scan ----
    float p = om[0] * om[1] * om[2] * om[3];
    float incl = p;
    #pragma unroll
    for (int off = 1; off < 32; off <<= 1) {
        float v = __shfl_up_sync(0xffffffffu, incl, off);
        if (lane >= off) incl *= v;
    }
    float T = __shfl_up_sync(0xffffffffu, incl, 1);  // exclusive prefix
    if (lane == 0) T = 1.0f;

    // ---- weights + composites ----
    float w[4];
    #pragma unroll
    for (int k = 0; k < 4; k++) {
        int i = lane * 4 + k;
        float wt = (alpha[k] + RM_EPS) * T;
        w[k] = wt;
        T *= om[k];
        if (i < S_INT) {
            wsum  += wt;
            wdsum += wt * dmid[k];
            float cm0 = 0.5f * (scol[3 * i + 0] + scol[3 * i + 3]);
            float cm1 = 0.5f * (scol[3 * i + 1] + scol[3 * i + 4]);
            float cm2 = 0.5f * (scol[3 * i + 2] + scol[3 * i + 5]);
            r0 += wt * cm0;
            r1 += wt * cm1;
            r2 += wt * cm2;
        }
    }

    // ---- warp reductions (5 scalars) ----
    #pragma unroll
    for (int off = 16; off; off >>= 1) {
        wsum  += __shfl_xor_sync(0xffffffffu, wsum, off);
        wdsum += __shfl_xor_sync(0xffffffffu, wdsum, off);
        r0    += __shfl_xor_sync(0xffffffffu, r0, off);
        r1    += __shfl_xor_sync(0xffffffffu, r1, off);
        r2    += __shfl_xor_sync(0xffffffffu, r2, off);
    }

    // ---- output offsets (flattened tuple, float32) ----
    const size_t NR      = (size_t)n_rays;
    const size_t OFF_RGB = 0;
    const size_t OFF_D   = 3 * NR;
    const size_t OFF_W   = 4 * NR;
    const size_t OFF_WA  = OFF_W  + NR * S_INT;
    const size_t OFF_A   = OFF_WA + NR * S_INT;
    const size_t OFF_DM  = OFF_A  + NR * S_INT;

    if (lane == 0) {
        out[OFF_RGB + (size_t)ray * 3 + 0] = r0 * 2.0f - 1.0f;
        out[OFF_RGB + (size_t)ray * 3 + 1] = r1 * 2.0f - 1.0f;
        out[OFF_RGB + (size_t)ray * 3 + 2] = r2 * 2.0f - 1.0f;
        float d = wdsum / (RM_EPS + wsum);
        if (!(d == d)) d = MAX_DEPTH;               // nan_to_num
        d = fminf(fmaxf(d, MIN_DEPTH), MAX_DEPTH);  // clip
        out[OFF_D + ray] = d;
    }

    // ---- stage per-interval outputs in shared, then coalesced writes ----
    __syncwarp();  // all scol reads done before we overwrite it
    float* sw  = scol;         // 127
    float* sa  = scol + 128;   // 127
    float* sdm = scol + 256;   // 127
    #pragma unroll
    for (int k = 0; k < 4; k++) {
        int i = lane * 4 + k;
        if (i < S_INT) { sw[i] = w[k]; sa[i] = alpha[k]; sdm[i] = dmid[k]; }
    }
    __syncwarp();

    const size_t rb = (size_t)ray * S_INT;
    #pragma unroll
    for (int k = 0; k < 4; k++) {
        int i = lane + 32 * k;
        if (i < S_INT) {
            float wv = sw[i], av = sa[i], dv = sdm[i];
            out[OFF_W  + rb + i] = wv;
            out[OFF_WA + rb + i] = wv;
            out[OFF_A  + rb + i] = av;
            out[OFF_DM + rb + i] = dv;
        }
    }
}

extern "C" void kernel_launch(void* const* d_in, const int* in_sizes, int n_in,
                              void* d_out, int out_size)
{
    const float* colors = (const float*)d_in[0];  // [B,R,S,3]
    const float* dlog   = (const float*)d_in[1];  // [B,R,S,1]
    const float* depths = (const float*)d_in[2];  // [B,R,S,1]
    float* out = (float*)d_out;

    int n_rays = in_sizes[1] / S_SAMP;            // B*R = 65536
    int blocks = (n_rays + WARPS_PER_BLOCK - 1) / WARPS_PER_BLOCK;
    mip_ray_marcher_kernel<<<blocks, WARPS_PER_BLOCK * 32>>>(
        colors, dlog, depths, out, n_rays);
}

// round 6
// speedup vs baseline: 1.0439x; 1.0439x over previous
#include <cuda_runtime.h>
#include <cuda_bf16.h>

#define RM_EPS 1e-10f
#define MIN_DEPTH 0.1f
#define MAX_DEPTH 100.0f

constexpr int S_SAMP = 128;        // samples per ray
constexpr int S_INT  = S_SAMP - 1; // 127 intervals
constexpr int WARPS_PER_BLOCK = 8;

// Per-warp shared layout (640 floats = 2560 B):
//   [0,384)   colors for this ray (128 samples * 3)
//   [384,512) density_logits
//   [512,640) depths
// Strided lane->interval mapping (lane l owns l, l+32, l+64, l+96) makes every
// shared read conflict-free (stride 1 or 3 across lanes) and every per-interval
// global store natively coalesced — no staging round-trip.
__global__ __launch_bounds__(WARPS_PER_BLOCK * 32)
void mip_ray_marcher_kernel(const float* __restrict__ colors,
                            const float* __restrict__ dlog,
                            const float* __restrict__ depths,
                            float* __restrict__ out,
                            int n_rays)
{
    __shared__ __align__(16) float smem[WARPS_PER_BLOCK][640];

    const int warp = threadIdx.x >> 5;
    const int lane = threadIdx.x & 31;
    const int ray  = blockIdx.x * WARPS_PER_BLOCK + warp;
    if (ray >= n_rays) return;

    float* scol = smem[warp];          // 384 floats
    float* sdl  = smem[warp] + 384;    // 128 floats
    float* sdep = smem[warp] + 512;    // 128 floats

    // ---- cooperative, coalesced float4 loads of this ray's data ----
    {
        const float4* c4 = (const float4*)(colors + (size_t)ray * (S_SAMP * 3));
        float4* s4 = (float4*)scol;
        s4[lane]      = c4[lane];
        s4[lane + 32] = c4[lane + 32];
        s4[lane + 64] = c4[lane + 64];

        const float4* d4 = (const float4*)(dlog + (size_t)ray * S_SAMP);
        ((float4*)sdl)[lane] = d4[lane];

        const float4* z4 = (const float4*)(depths + (size_t)ray * S_SAMP);
        ((float4*)sdep)[lane] = z4[lane];
    }
    __syncwarp();

    // ---- output offsets (flattened tuple, float32) ----
    const size_t NR      = (size_t)n_rays;
    const size_t OFF_RGB = 0;
    const size_t OFF_D   = 3 * NR;
    const size_t OFF_W   = 4 * NR;
    const size_t OFF_WA  = OFF_W  + NR * S_INT;
    const size_t OFF_A   = OFF_WA + NR * S_INT;
    const size_t OFF_DM  = OFF_A  + NR * S_INT;
    const size_t rb      = (size_t)ray * S_INT;

    float r0 = 0.f, r1 = 0.f, r2 = 0.f, wsum = 0.f, wdsum = 0.f;
    float carry = 1.0f;   // transmittance entering this chunk of 32 intervals

    #pragma unroll
    for (int k = 0; k < 4; k++) {
        const int  i     = lane + 32 * k;
        const bool valid = (i < S_INT);          // false only for lane31,k=3
        const int  il    = valid ? i : (S_INT - 1);

        // conflict-free shared reads (stride 1 across lanes)
        float dl0 = sdl[il],  dl1 = sdl[il + 1];
        float z0  = sdep[il], z1  = sdep[il + 1];

        float dlm  = 0.5f * (dl0 + dl1) - 1.0f;
        // numerically stable softplus: max(x,0) + log1p(exp(-|x|))
        float dens = fmaxf(dlm, 0.0f) + log1pf(expf(-fabsf(dlm)));
        float a    = valid ? (1.0f - expf(-dens * (z1 - z0))) : 0.0f;
        float om   = valid ? (1.0f - a + RM_EPS) : 1.0f;   // scan identity
        float dmid = 0.5f * (z0 + z1);

        // warp inclusive cumprod over this chunk of 32 intervals
        float incl = om;
        #pragma unroll
        for (int off = 1; off < 32; off <<= 1) {
            float v = __shfl_up_sync(0xffffffffu, incl, off);
            if (lane >= off) incl *= v;
        }
        float excl = __shfl_up_sync(0xffffffffu, incl, 1);
        if (lane == 0) excl = 1.0f;
        float T = carry * excl;
        carry *= __shfl_sync(0xffffffffu, incl, 31);   // chunk total product

        float wt = (a + RM_EPS) * T;

        if (valid) {
            wsum  += wt;
            wdsum += wt * dmid;
            // stride-3 across lanes -> conflict-free
            float cm0 = 0.5f * (scol[3 * i + 0] + scol[3 * i + 3]);
            float cm1 = 0.5f * (scol[3 * i + 1] + scol[3 * i + 4]);
            float cm2 = 0.5f * (scol[3 * i + 2] + scol[3 * i + 5]);
            r0 += wt * cm0;
            r1 += wt * cm1;
            r2 += wt * cm2;

            // natively coalesced per-interval stores
            out[OFF_W  + rb + i] = wt;
            out[OFF_WA + rb + i] = wt;
            out[OFF_A  + rb + i] = a;
            out[OFF_DM + rb + i] = dmid;
        }
    }

    // ---- warp reductions (5 scalars) ----
    #pragma unroll
    for (int off = 16; off; off >>= 1) {
        wsum  += __shfl_xor_sync(0xffffffffu, wsum, off);
        wdsum += __shfl_xor_sync(0xffffffffu, wdsum, off);
        r0    += __shfl_xor_sync(0xffffffffu, r0, off);
        r1    += __shfl_xor_sync(0xffffffffu, r1, off);
        r2    += __shfl_xor_sync(0xffffffffu, r2, off);
    }

    if (lane == 0) {
        out[OFF_RGB + (size_t)ray * 3 + 0] = r0 * 2.0f - 1.0f;
        out[OFF_RGB + (size_t)ray * 3 + 1] = r1 * 2.0f - 1.0f;
        out[OFF_RGB + (size_t)ray * 3 + 2] = r2 * 2.0f - 1.0f;
        float d = wdsum / (RM_EPS + wsum);
        if (!(d == d)) d = MAX_DEPTH;               // nan_to_num
        d = fminf(fmaxf(d, MIN_DEPTH), MAX_DEPTH);  // clip
        out[OFF_D + ray] = d;
    }
}

extern "C" void kernel_launch(void* const* d_in, const int* in_sizes, int n_in,
                              void* d_out, int out_size)
{
    const float* colors = (const float*)d_in[0];  // [B,R,S,3]
    const float* dlog   = (const float*)d_in[1];  // [B,R,S,1]
    const float* depths = (const float*)d_in[2];  // [B,R,S,1]
    float* out = (float*)d_out;

    int n_rays = in_sizes[1] / S_SAMP;            // B*R = 65536
    int blocks = (n_rays + WARPS_PER_BLOCK - 1) / WARPS_PER_BLOCK;
    mip_ray_marcher_kernel<<<blocks, WARPS_PER_BLOCK * 32>>>(
        colors, dlog, depths, out, n_rays);
}